// round 16
// baseline (speedup 1.0000x reference)
#include <cuda_runtime.h>
#include <cuda_bf16.h>
#include <mma.h>
#include <cstdint>

using namespace nvcuda;
typedef __nv_bfloat16 bf16;
typedef unsigned int uint;

__device__ __forceinline__ float sigmoidf(float x) {
    return __fdividef(1.0f, 1.0f + __expf(-x));
}
// bf16 hi/lo split: v = h + l + O(2^-18 v)
__device__ __forceinline__ void bsplit(float v, bf16& h, bf16& l) {
    h = __float2bfloat16(v);
    l = __float2bfloat16(v - __bfloat162float(h));
}

typedef wmma::fragment<wmma::accumulator, 16, 16, 16, float> FragC;
typedef wmma::fragment<wmma::matrix_a, 16, 16, 16, bf16, wmma::row_major> FragA;

// Warp-local: 16x16 fp32 frag -> scratch -> bf16 hi/lo region (stride 72)
__device__ __forceinline__ void conv_frag(float* scr, const FragC& cf,
                                          bf16* dh, bf16* dl, int lane) {
    wmma::store_matrix_sync(scr, cf, 20, wmma::mem_row_major);
    __syncwarp();
#pragma unroll
    for (int e = 0; e < 8; e += 2) {
        int idx = lane * 8 + e;
        int row = idx >> 4, col = idx & 15;
        float v0 = scr[row * 20 + col], v1 = scr[row * 20 + col + 1];
        bf16 h0, l0, h1, l1;
        bsplit(v0, h0, l0); bsplit(v1, h1, l1);
        *(__nv_bfloat162*)(dh + row * 72 + col) = __nv_bfloat162(h0, h1);
        *(__nv_bfloat162*)(dl + row * 72 + col) = __nv_bfloat162(l0, l1);
    }
    __syncwarp();
}

__device__ __forceinline__ void sum3(FragC& d, const FragC s[3]) {
#pragma unroll
    for (int i = 0; i < d.num_elements; ++i)
        d.x[i] = s[0].x[i] + s[1].x[i] + s[2].x[i];
}

__device__ __forceinline__ void st_cluster_b32(uint32_t laddr, uint peer, uint v) {
    uint32_t raddr;
    asm("mapa.shared::cluster.u32 %0, %1, %2;" : "=r"(raddr) : "r"(laddr), "r"(peer));
    asm volatile("st.shared::cluster.b32 [%0], %1;" :: "r"(raddr), "r"(v) : "memory");
}

// xg scratch: [l][g][n][a][b]  (384 MB device .bss)
__device__ float g_xg[(size_t)3 * 128 * 64 * 64 * 64];

// ============================================================================
// Phase 1 (unchanged R14 — validated): gates-parallel wmma, split-term accs.
// ============================================================================
#define XG_XH   0
#define XG_XL   18432
#define XG_W2H  36864
#define XG_W2L  64512
#define XG_W1H  92160
#define XG_W1L  119808
#define XG_TH   147456
#define XG_TL   175104
#define XG_SCR  202752
#define XG_SMEM 218112

__global__ void __launch_bounds__(384, 1)
xg_kernel(const float* __restrict__ inputs,
          const float* __restrict__ Ww1,
          const float* __restrict__ Ww2) {
    extern __shared__ char smx[];
    bf16* XH  = (bf16*)(smx + XG_XH);
    bf16* XL  = (bf16*)(smx + XG_XL);
    bf16* W2H = (bf16*)(smx + XG_W2H);
    bf16* W2L = (bf16*)(smx + XG_W2L);
    bf16* W1H = (bf16*)(smx + XG_W1H);
    bf16* W1L = (bf16*)(smx + XG_W1L);
    bf16* TH  = (bf16*)(smx + XG_TH);
    bf16* TL  = (bf16*)(smx + XG_TL);

    const int tid = threadIdx.x;
    const int w = tid >> 5, lane = tid & 31;
    const int g = w >> 2, mt = w & 3;
    float* scr = (float*)(smx + XG_SCR) + w * 320;

    for (int e = tid; e < 12288; e += 384) {
        int gg = e >> 12, r = (e >> 6) & 63, c = e & 63;
        bf16 h, l;
        bsplit(Ww2[e], h, l);
        W2H[gg * 4608 + r * 72 + c] = h;
        W2L[gg * 4608 + r * 72 + c] = l;
        bsplit(Ww1[e], h, l);
        W1H[gg * 4608 + r * 72 + c] = h;
        W1L[gg * 4608 + r * 72 + c] = l;
    }
    __syncthreads();

    for (int t = 0; t < 8; ++t) {
        const int flat = blockIdx.x * 8 + t;
        const int l = flat >> 6, n = flat & 63;

        const float* xsrc = inputs + ((size_t)n * 128 + l) * 4096;
        for (int e = tid; e < 4096; e += 384) {
            int i = e >> 6, j = e & 63;
            bf16 h, lo; bsplit(xsrc[e], h, lo);
            XH[i * 72 + j] = h;
            XL[i * 72 + j] = lo;
        }
        __syncthreads();

        // stage A: T_g[i,b], two passes of 2 nt; per-acc chain = 4
        for (int half = 0; half < 2; ++half) {
            FragC s[2][3];
#pragma unroll
            for (int nt = 0; nt < 2; ++nt)
#pragma unroll
                for (int tm = 0; tm < 3; ++tm) wmma::fill_fragment(s[nt][tm], 0.0f);
#pragma unroll
            for (int k = 0; k < 4; ++k) {
                FragA ah, al;
                wmma::load_matrix_sync(ah, XH + mt * 16 * 72 + k * 16, 72);
                wmma::load_matrix_sync(al, XL + mt * 16 * 72 + k * 16, 72);
#pragma unroll
                for (int nt = 0; nt < 2; ++nt) {
                    int ntg = half * 2 + nt;
                    wmma::fragment<wmma::matrix_b, 16, 16, 16, bf16, wmma::col_major> bh, bl;
                    wmma::load_matrix_sync(bh, W2H + g * 4608 + ntg * 16 * 72 + k * 16, 72);
                    wmma::load_matrix_sync(bl, W2L + g * 4608 + ntg * 16 * 72 + k * 16, 72);
                    wmma::mma_sync(s[nt][0], ah, bh, s[nt][0]);
                    wmma::mma_sync(s[nt][1], ah, bl, s[nt][1]);
                    wmma::mma_sync(s[nt][2], al, bh, s[nt][2]);
                }
            }
#pragma unroll
            for (int nt = 0; nt < 2; ++nt) {
                FragC d; sum3(d, s[nt]);
                int ntg = half * 2 + nt;
                conv_frag(scr, d,
                          TH + g * 4608 + mt * 16 * 72 + ntg * 16,
                          TL + g * 4608 + mt * 16 * 72 + ntg * 16, lane);
            }
        }
        __syncthreads();

        // stage B -> global
        for (int half = 0; half < 2; ++half) {
            FragC s[2][3];
#pragma unroll
            for (int nt = 0; nt < 2; ++nt)
#pragma unroll
                for (int tm = 0; tm < 3; ++tm) wmma::fill_fragment(s[nt][tm], 0.0f);
#pragma unroll
            for (int k = 0; k < 4; ++k) {
                FragA ah, al;
                wmma::load_matrix_sync(ah, W1H + g * 4608 + mt * 16 * 72 + k * 16, 72);
                wmma::load_matrix_sync(al, W1L + g * 4608 + mt * 16 * 72 + k * 16, 72);
#pragma unroll
                for (int nt = 0; nt < 2; ++nt) {
                    int ntg = half * 2 + nt;
                    wmma::fragment<wmma::matrix_b, 16, 16, 16, bf16, wmma::row_major> bh, bl;
                    wmma::load_matrix_sync(bh, TH + g * 4608 + k * 16 * 72 + ntg * 16, 72);
                    wmma::load_matrix_sync(bl, TL + g * 4608 + k * 16 * 72 + ntg * 16, 72);
                    wmma::mma_sync(s[nt][0], ah, bh, s[nt][0]);
                    wmma::mma_sync(s[nt][1], ah, bl, s[nt][1]);
                    wmma::mma_sync(s[nt][2], al, bh, s[nt][2]);
                }
            }
            float* dst = g_xg + ((size_t)(l * 3 + g) * 64 + n) * 4096 + mt * 16 * 64;
#pragma unroll
            for (int nt = 0; nt < 2; ++nt) {
                FragC d; sum3(d, s[nt]);
                wmma::store_matrix_sync(dst + (half * 2 + nt) * 16, d, 64,
                                        wmma::mem_row_major);
            }
        }
        __syncthreads();
    }
}

// ============================================================================
// Phase 2: cluster-2, 384 threads. Stage1 = 12 warps (R14). Stage2 = 8 warps,
// each a 16x16 (mt2, b-quarter) region x all 3 gates, term-0 accumulators
// initialized from g_xg fragment loads, in-fragment elementwise.
// 1 CTA sync + 1 cluster barrier per step.
// ============================================================================
#define RC_HB0H  0          // [64][72] bf16
#define RC_HB0L  9216
#define RC_HB1H  18432
#define RC_HB1L  27648
#define RC_W1H   36864      // [3][32][72] bf16
#define RC_W1L   50688
#define RC_W2H   64512      // [3][64][72] bf16
#define RC_W2L   92160
#define RC_TH    119808     // [3][32][72] bf16
#define RC_TL    133632
#define RC_SCR   147456     // 12 x 320 fp32
#define RC_SMEM  162816

__global__ void __launch_bounds__(384, 1) __cluster_dims__(2, 1, 1)
rec_kernel(const float* __restrict__ Wu1,
           const float* __restrict__ Wu2,
           float* __restrict__ out) {
    extern __shared__ char smx[];
    bf16* W1H = (bf16*)(smx + RC_W1H);
    bf16* W1L = (bf16*)(smx + RC_W1L);
    bf16* W2H = (bf16*)(smx + RC_W2H);
    bf16* W2L = (bf16*)(smx + RC_W2L);
    bf16* TH  = (bf16*)(smx + RC_TH);
    bf16* TL  = (bf16*)(smx + RC_TL);

    const int bid  = blockIdx.x;
    const int n    = bid >> 1;
    const int rank = bid & 1;
    const int tid  = threadIdx.x;
    const int w = tid >> 5, lane = tid & 31;
    // stage1 roles (12 warps): (gw, mtw, hw)
    const int gw = w >> 2, mtw = (w >> 1) & 1, hw = w & 1;
    // stage2 roles (warps 0..7): (mt2, q2)
    const int mt2 = w >> 2, q2 = w & 3;
    float* scrw = (float*)(smx + RC_SCR) + w * 320;

    uint32_t sbase;
    asm("{ .reg .u64 t; cvta.to.shared.u64 t, %1; cvt.u32.u64 %0, t; }"
        : "=r"(sbase) : "l"(smx));
    const uint peer = rank ^ 1;

    // weights: W1 = own 32 a-rows; W2 = full
    for (int e = tid; e < 6144; e += 384) {
        int gg = e >> 11, al = (e >> 6) & 31, i = e & 63;
        bf16 h, l;
        bsplit(Wu1[gg * 4096 + (32 * rank + al) * 64 + i], h, l);
        W1H[gg * 2304 + al * 72 + i] = h;
        W1L[gg * 2304 + al * 72 + i] = l;
    }
    for (int e = tid; e < 12288; e += 384) {
        int gg = e >> 12, b = (e >> 6) & 63, j = e & 63;
        bf16 h, l;
        bsplit(Wu2[gg * 4096 + b * 64 + j], h, l);
        W2H[gg * 4608 + b * 72 + j] = h;
        W2L[gg * 4608 + b * 72 + j] = l;
    }
    for (int e = tid; e < 18432; e += 384)   // zero both h ping-pong buffers
        ((bf16*)smx)[e] = __float2bfloat16(0.f);

    float cst[8];
#pragma unroll
    for (int e = 0; e < 8; ++e) cst[e] = 0.f;

    __syncthreads();
    asm volatile("barrier.cluster.arrive.aligned;" ::: "memory");
    asm volatile("barrier.cluster.wait.aligned;"   ::: "memory");

    for (int l = 0; l < 128; ++l) {
        bf16* hTH = (bf16*)(smx + ((l & 1) ? RC_HB1H : RC_HB0H));
        bf16* hTL = (bf16*)(smx + ((l & 1) ? RC_HB1L : RC_HB0L));
        const int hNoffH = (l & 1) ? RC_HB0H : RC_HB1H;
        const int hNoffL = (l & 1) ? RC_HB0L : RC_HB1L;
        bf16* hNH = (bf16*)(smx + hNoffH);
        bf16* hNL = (bf16*)(smx + hNoffL);

        // ---- stage1: warp (gw, mtw, hw): tmp rows 16*mtw, cols 32*hw ----
        {
            FragC s[2][3];
#pragma unroll
            for (int nt = 0; nt < 2; ++nt)
#pragma unroll
                for (int tm = 0; tm < 3; ++tm) wmma::fill_fragment(s[nt][tm], 0.0f);
#pragma unroll
            for (int k = 0; k < 4; ++k) {
                FragA ah, al;
                wmma::load_matrix_sync(ah, W1H + gw * 2304 + mtw * 16 * 72 + k * 16, 72);
                wmma::load_matrix_sync(al, W1L + gw * 2304 + mtw * 16 * 72 + k * 16, 72);
#pragma unroll
                for (int nt = 0; nt < 2; ++nt) {
                    int ntg = hw * 2 + nt;
                    wmma::fragment<wmma::matrix_b, 16, 16, 16, bf16, wmma::row_major> bh, bl;
                    wmma::load_matrix_sync(bh, hTH + k * 16 * 72 + ntg * 16, 72);
                    wmma::load_matrix_sync(bl, hTL + k * 16 * 72 + ntg * 16, 72);
                    wmma::mma_sync(s[nt][0], ah, bh, s[nt][0]);
                    wmma::mma_sync(s[nt][1], ah, bl, s[nt][1]);
                    wmma::mma_sync(s[nt][2], al, bh, s[nt][2]);
                }
            }
#pragma unroll
            for (int nt = 0; nt < 2; ++nt) {
                FragC d; sum3(d, s[nt]);
                int ntg = hw * 2 + nt;
                conv_frag(scrw, d,
                          TH + gw * 2304 + mtw * 16 * 72 + ntg * 16,
                          TL + gw * 2304 + mtw * 16 * 72 + ntg * 16, lane);
            }
        }
        __syncthreads();

        // ---- stage2 + elementwise: warps 0..7, 16x16 region (mt2, q2) ----
        if (w < 8) {
            FragC s[3][3];
            // term-0 accumulators start as xg (global fragment loads; the
            // latency overlaps the 72-HMMA issue stream below)
#pragma unroll
            for (int gg = 0; gg < 3; ++gg) {
                wmma::load_matrix_sync(s[gg][0],
                    g_xg + ((size_t)(l * 3 + gg) * 64 + n) * 4096
                         + (size_t)(32 * rank + mt2 * 16) * 64 + q2 * 16,
                    64, wmma::mem_row_major);
                wmma::fill_fragment(s[gg][1], 0.0f);
                wmma::fill_fragment(s[gg][2], 0.0f);
            }
#pragma unroll
            for (int gg = 0; gg < 3; ++gg) {
#pragma unroll
                for (int k = 0; k < 4; ++k) {
                    FragA ah, al;
                    wmma::load_matrix_sync(ah, TH + gg * 2304 + mt2 * 16 * 72 + k * 16, 72);
                    wmma::load_matrix_sync(al, TL + gg * 2304 + mt2 * 16 * 72 + k * 16, 72);
                    wmma::fragment<wmma::matrix_b, 16, 16, 16, bf16, wmma::col_major> bh, bl;
                    wmma::load_matrix_sync(bh, W2H + gg * 4608 + q2 * 16 * 72 + k * 16, 72);
                    wmma::load_matrix_sync(bl, W2L + gg * 4608 + q2 * 16 * 72 + k * 16, 72);
                    wmma::mma_sync(s[gg][0], ah, bh, s[gg][0]);
                    wmma::mma_sync(s[gg][1], ah, bl, s[gg][1]);
                    wmma::mma_sync(s[gg][2], al, bh, s[gg][2]);
                }
            }
            FragC dz, dr, dof;
            sum3(dz, s[0]); sum3(dr, s[1]); sum3(dof, s[2]);
            // elementwise in registers (identical accumulator layouts)
#pragma unroll
            for (int i = 0; i < 8; ++i) {
                float z = sigmoidf(dz.x[i]);
                float r = sigmoidf(dr.x[i]);
                float o = sigmoidf(dof.x[i]);
                float cn = r * (cst[i] + z);     // c = r*c + z*r
                cst[i] = cn;
                dz.x[i] = o * sigmoidf(cn);      // h
            }
            wmma::store_matrix_sync(scrw, dz, 20, wmma::mem_row_major);
            __syncwarp();
            float* orow = out + ((size_t)n * 128 + l) * 4096;
#pragma unroll
            for (int e = 0; e < 8; e += 2) {
                int idx = lane * 8 + e;
                int row = idx >> 4, col = idx & 15;
                int ag = 32 * rank + mt2 * 16 + row;
                int b = q2 * 16 + col;
                float v0 = scrw[row * 20 + col], v1 = scrw[row * 20 + col + 1];
                *(float2*)(orow + ag * 64 + b) = make_float2(v0, v1);
                bf16 h0, l0, h1, l1;
                bsplit(v0, h0, l0); bsplit(v1, h1, l1);
                __nv_bfloat162 hw2 = __nv_bfloat162(h0, h1);
                __nv_bfloat162 lw2 = __nv_bfloat162(l0, l1);
                uint off = (uint)(ag * 72 + b) * 2;
                *(__nv_bfloat162*)(hNH + ag * 72 + b) = hw2;
                *(__nv_bfloat162*)(hNL + ag * 72 + b) = lw2;
                st_cluster_b32(sbase + hNoffH + off, peer, *(uint*)&hw2);
                st_cluster_b32(sbase + hNoffL + off, peer, *(uint*)&lw2);
            }
            __syncwarp();
        }
        asm volatile("barrier.cluster.arrive.aligned;" ::: "memory");
        asm volatile("barrier.cluster.wait.aligned;"   ::: "memory");
    }

    // epilogue: h_last = own half of outs[:,127]; c_last from cst via scratch
    {
        const float* hsrc = out + ((size_t)n * 128 + 127) * 4096 + rank * 2048;
        float* hl = out + 33554432ull + (size_t)n * 4096 + rank * 2048;
        for (int e = tid; e < 2048; e += 384) hl[e] = hsrc[e];
        if (w < 8) {
            float* cl = out + 33816576ull + (size_t)n * 4096;
            FragC cf;
#pragma unroll
            for (int i = 0; i < 8; ++i) cf.x[i] = cst[i];
            wmma::store_matrix_sync(scrw, cf, 20, wmma::mem_row_major);
            __syncwarp();
#pragma unroll
            for (int e = 0; e < 8; e += 2) {
                int idx = lane * 8 + e;
                int row = idx >> 4, col = idx & 15;
                int ag = 32 * rank + mt2 * 16 + row;
                int b = q2 * 16 + col;
                *(float2*)(cl + ag * 64 + b) =
                    make_float2(scrw[row * 20 + col], scrw[row * 20 + col + 1]);
            }
            __syncwarp();
        }
    }
}

// ============================================================================
extern "C" void kernel_launch(void* const* d_in, const int* in_sizes, int n_in,
                              void* d_out, int out_size) {
    const float* inputs = (const float*)d_in[0];   // (64,128,64,64)
    const float* Ww1    = (const float*)d_in[1];   // (4,64,64) — g<3 used
    const float* Ww2    = (const float*)d_in[2];
    const float* Wu1    = (const float*)d_in[3];
    const float* Wu2    = (const float*)d_in[4];
    float* out = (float*)d_out;

    cudaFuncSetAttribute(xg_kernel,  cudaFuncAttributeMaxDynamicSharedMemorySize, XG_SMEM);
    cudaFuncSetAttribute(rec_kernel, cudaFuncAttributeMaxDynamicSharedMemorySize, RC_SMEM);

    xg_kernel<<<1024, 384, XG_SMEM>>>(inputs, Ww1, Ww2);
    rec_kernel<<<128, 384, RC_SMEM>>>(Wu1, Wu2, out);
}